// round 6
// baseline (speedup 1.0000x reference)
#include <cuda_runtime.h>
#include <math.h>

// ---------------- scratch ----------------
__device__ __align__(16) float2 g_s2[8388608];  // [4][64][32][8][128] complex workspace (in-place)
__device__ __align__(16) float  g_W[8192];      // [4 mats][8 blk][16][16] folded MLP weights
__device__ __align__(16) float  g_Bias[512];    // [4][8][16] folded biases
// tf32 twiddle A-matrices, mma pairing layout: idx=((mat*KT+kk)*M+m)*8+klm*2+khi, k=kk*8+khi*4+klm
__device__ __align__(16) float  g_TA_L[512];    // fwd L: M=16(2l+pp),K=32(t), 1/sqrt(32) baked
__device__ __align__(16) float  g_TA_W[4096];   // fwd W/H: cos|sin, M=32,K=64, 1/8 baked
__device__ __align__(16) float  g_TA_Wi[4096];  // inv W/H: cos|sin, M=64,K=32, 1/8 baked
__device__ __align__(16) float  g_TA_Li[512];   // inv L: M=32(t),K=16(2l+pp), 1/sqrt(32)*[1|2] baked

__device__ __forceinline__ float gelu_f(float v){
  return 0.5f*v*(1.0f+erff(v*0.7071067811865476f));
}
__device__ __forceinline__ float tf32f(float f){
  unsigned u; asm("cvt.rna.tf32.f32 %0, %1;" : "=r"(u) : "f"(f));
  return __uint_as_float(u);
}
__device__ __forceinline__ void mma8(float4& d, float a0, float a1, float a2, float a3,
                                     float b0, float b1){
  asm volatile("mma.sync.aligned.m16n8k8.row.col.f32.tf32.tf32.f32 "
    "{%0,%1,%2,%3}, {%4,%5,%6,%7}, {%8,%9}, {%0,%1,%2,%3};"
    : "+f"(d.x), "+f"(d.y), "+f"(d.z), "+f"(d.w)
    : "r"(__float_as_uint(a0)), "r"(__float_as_uint(a1)),
      "r"(__float_as_uint(a2)), "r"(__float_as_uint(a3)),
      "r"(__float_as_uint(b0)), "r"(__float_as_uint(b1)));
}

// ---------------- K0a: build twiddle matrices ----------------
__global__ void k_init_T(){
  int idx = blockIdx.x*256 + threadIdx.x;   // 9216
  const double s32 = 0.17677669529663688911;
  if (idx < 512){
    int j = idx; int khi=j&1, klm=(j>>1)&3, m=(j>>3)&15, kk=j>>7;
    int t = kk*8+khi*4+klm; int l = m>>1, pp = m&1;
    double a = (double)(t*l)/16.0;
    g_TA_L[j] = tf32f((float)((pp==0 ? cospi(a) : -sinpi(a))*s32));
  } else if (idx < 4608){
    int j = idx-512; int khi=j&1, klm=(j>>1)&3, m=(j>>3)&31, kk=(j>>8)&7, mat=j>>11;
    int k = kk*8+khi*4+klm;
    double a = (double)(m*k)/32.0;
    g_TA_W[j] = tf32f((float)((mat ? sinpi(a) : cospi(a))*0.125));
  } else if (idx < 8704){
    int j = idx-4608; int khi=j&1, klm=(j>>1)&3, m=(j>>3)&63, kk=(j>>9)&3, mat=j>>11;
    int k = kk*8+khi*4+klm;
    double a = (double)(m*k)/32.0;
    g_TA_Wi[j] = tf32f((float)((mat ? sinpi(a) : cospi(a))*0.125));
  } else if (idx < 9216){
    int j = idx-8704; int khi=j&1, klm=(j>>1)&3, t=(j>>3)&31, kk=j>>8;
    int k2 = kk*8+khi*4+klm; int l = k2>>1, pp = k2&1;
    double cl = (l==0)?1.0:2.0;
    double a = (double)(t*l)/16.0;
    g_TA_Li[j] = tf32f((float)((pp==0 ? cl*cospi(a) : -cl*sinpi(a))*s32));
  }
}

// ---------------- K0: fold HydraLoRA ----------------
__global__ void k_prep(const float* __restrict__ w1, const float* __restrict__ b1,
                       const float* __restrict__ w2, const float* __restrict__ b2,
                       const float* __restrict__ A1r, const float* __restrict__ B1r,
                       const float* __restrict__ A1i, const float* __restrict__ B1i,
                       const float* __restrict__ A2r, const float* __restrict__ B2r,
                       const float* __restrict__ A2i, const float* __restrict__ B2i,
                       const float* __restrict__ ew){
  int k  = blockIdx.x;        // block 0..7
  int io = threadIdx.x;       // 0..255
  int i = io >> 4, o = io & 15;
  float e0 = ew[0], e1 = ew[1], e2 = ew[2], e3 = ew[3];
  const float s = 0.03125f;   // ALPHA/R
  const float* Ws[4] = { w1 + k*256, w1 + 2048 + k*256, w2 + k*256, w2 + 2048 + k*256 };
  const float* As[4] = { A1r + k*512, A1i + k*512, A2r + k*512, A2i + k*512 };
  const float* Bs[4] = { B1r + k*2048, B1i + k*2048, B2r + k*2048, B2i + k*2048 };
#pragma unroll
  for (int m = 0; m < 4; m++){
    const float* A  = As[m] + i*32;
    const float* Bb = Bs[m];
    float acc = 0.f;
    for (int r = 0; r < 32; r++){
      float bm = e0*Bb[r*16+o] + e1*Bb[512+r*16+o] + e2*Bb[1024+r*16+o] + e3*Bb[1536+r*16+o];
      acc = fmaf(A[r], bm, acc);
    }
    g_W[((m*8+k)*16+i)*16+o] = Ws[m][i*16+o] + s*acc;
  }
  if (io < 16){
    float b10 = b1[k*16+io], b11 = b1[128+k*16+io];
    float b20 = b2[k*16+io], b21 = b2[128+k*16+io];
    g_Bias[      k*16+io] = b10 - b11;
    g_Bias[128 + k*16+io] = b10 + b11;
    g_Bias[256 + k*16+io] = b20 - b21;
    g_Bias[384 + k*16+io] = b20 + b21;
  }
}

// ================= K1: fused forward (L-rfft GEMM + W-DFT GEMM) =================
// grid (ct=16, y=64, b=4), 256 thr. smem: sA_L[512]|sA_W[4096]|U[16512]
__global__ void __launch_bounds__(256) k_fwd(const float* __restrict__ x){
  extern __shared__ float sm[];
  float* sA_L = sm;
  float* sA_W = sm + 512;
  float* U    = sm + 4608;    // B1: 16 slices x 1032; later B2: 32 slices x 264
  int tid = threadIdx.x;
  int ct = blockIdx.x, y = blockIdx.y, b = blockIdx.z;
  for (int i=tid; i<128;  i+=256) ((float4*)sA_L)[i] = ((const float4*)g_TA_L)[i];
  for (int i=tid; i<1024; i+=256) ((float4*)sA_W)[i] = ((const float4*)g_TA_W)[i];
  const float* xb = x + (size_t)(b*64+y)*262144 + ct*8;
  for (int i=tid; i<4096; i+=256){
    int xx=i>>6, r=i&63, t=r>>1, half=r&1;
    float4 v = *(const float4*)(xb + (size_t)xx*4096 + t*128 + half*4);
    float* d = U + ((t>>3)*4+(t&3))*1032 + ((t>>2)&1) + (xx*8+half*4)*2;
    d[0]=tf32f(v.x); d[2]=tf32f(v.y); d[4]=tf32f(v.z); d[6]=tf32f(v.w);
  }
  __syncthreads();
  int warp=tid>>5, lane=tid&31, qid=lane>>2, rid=lane&3;
  // phase1: L GEMM M=16,K=32,N=512 (n1 = xx*8+c)
  float4 C1[8];
#pragma unroll
  for (int nt=0;nt<8;nt++) C1[nt] = make_float4(0.f,0.f,0.f,0.f);
#pragma unroll
  for (int kk=0; kk<4; kk++){
    const float* Ap = sA_L + kk*128;
    float2 a02 = *(const float2*)(Ap + qid*8 + rid*2);
    float2 a13 = *(const float2*)(Ap + (qid+8)*8 + rid*2);
    const float* Bp = U + (kk*4+rid)*1032;
#pragma unroll
    for (int nt=0; nt<8; nt++){
      float2 bf = *(const float2*)(Bp + (warp*64+nt*8+qid)*2);
      mma8(C1[nt], a02.x, a13.x, a02.y, a13.y, bf.x, bf.y);
    }
  }
  __syncthreads();
  // scatter to B2[k2=xx][n2=(l*8+c)*2+pp]
  {
    int l0=qid>>1, pp=qid&1;
#pragma unroll
    for (int nt=0; nt<8; nt++){
      int n1 = warp*64+nt*8+rid*2, xx=n1>>3, c=n1&7;
      float* bp = U + ((xx>>3)*4+(xx&3))*264 + ((xx>>2)&1);
      bp[((l0*8+c  )*2+pp)*2]     = tf32f(C1[nt].x);
      bp[((l0*8+c+1)*2+pp)*2]     = tf32f(C1[nt].y);
      bp[(((l0+4)*8+c  )*2+pp)*2] = tf32f(C1[nt].z);
      bp[(((l0+4)*8+c+1)*2+pp)*2] = tf32f(C1[nt].w);
    }
  }
  __syncthreads();
  // phase2: W cos/sin GEMMs M=32,K=64,N=128
  float4 C2[2][2][2];
#pragma unroll
  for (int a=0;a<2;a++)
#pragma unroll
    for (int m=0;m<2;m++)
#pragma unroll
      for (int n=0;n<2;n++) C2[a][m][n] = make_float4(0.f,0.f,0.f,0.f);
#pragma unroll
  for (int kk=0; kk<8; kk++){
    const float* Bp = U + (kk*4+rid)*264;
    float2 bf0 = *(const float2*)(Bp + (warp*16+qid)*2);
    float2 bf1 = *(const float2*)(Bp + (warp*16+8+qid)*2);
#pragma unroll
    for (int mat=0; mat<2; mat++){
      const float* Ap = sA_W + (mat*8+kk)*256;
#pragma unroll
      for (int mt=0; mt<2; mt++){
        float2 a02 = *(const float2*)(Ap + (mt*16+qid)*8 + rid*2);
        float2 a13 = *(const float2*)(Ap + (mt*16+qid+8)*8 + rid*2);
        mma8(C2[mat][mt][0], a02.x,a13.x,a02.y,a13.y, bf0.x, bf0.y);
        mma8(C2[mat][mt][1], a02.x,a13.x,a02.y,a13.y, bf1.x, bf1.y);
      }
    }
  }
  float2* os = g_s2 + (size_t)(b*64+y)*32768 + ct*8;
#pragma unroll
  for (int mt=0; mt<2; mt++)
#pragma unroll
    for (int nt=0; nt<2; nt++){
      float4 cc = C2[0][mt][nt], cs = C2[1][mt][nt];
      int lc = warp*8+nt*4+rid, l=lc>>3, c=lc&7, w0=mt*16+qid;
      os[(size_t)w0*1024 + l*128 + c]     = make_float2(cc.x+cs.y, cc.y-cs.x);
      os[(size_t)(w0+8)*1024 + l*128 + c] = make_float2(cc.z+cs.w, cc.w-cs.z);
    }
}

// ================= K2: fused middle (fwd-H + MLP + inv-H), in-place =================
// grid (512 = w*16+l*2+chalf, b=4), 256 thr.
__global__ void __launch_bounds__(256) k_mid(){
  extern __shared__ float sm[];
  float* sA_W  = sm;            // 4096
  float* sA_Wi = sm + 4096;     // 4096
  float* sW    = sm + 8192;     // 4096
  float* sBias = sm + 12288;    // 272
  float* U     = sm + 12560;    // 8448 (B1h 32x264 -> sSpec 32x65 f2)
  float* U2    = sm + 21008;    // 4224 (B2h 16x264)
  int tid = threadIdx.x;
  int bx = blockIdx.x, b = blockIdx.y;
  int w = bx>>4, l = (bx>>1)&7, chalf = bx&1;
  for (int i=tid; i<1024; i+=256) ((float4*)sA_W)[i]  = ((const float4*)g_TA_W)[i];
  for (int i=tid; i<1024; i+=256) ((float4*)sA_Wi)[i] = ((const float4*)g_TA_Wi)[i];
  for (int i=tid; i<1024; i+=256){
    int mg=i>>8, nb0=(i>>6)&3;
    ((float4*)sW)[i] = ((const float4*)g_W)[(mg*8+chalf*4+nb0)*64 + (i&63)];
  }
  { int mg=tid>>6, nb0=(tid>>4)&3, o=tid&15;
    sBias[(mg*4+nb0)*17+o] = g_Bias[mg*128 + (chalf*4+nb0)*16 + o]; }
  float2* gs = g_s2 + (size_t)b*2097152 + (size_t)w*1024 + l*128 + chalf*64;
  for (int i=tid; i<4096; i+=256){
    int yy=i>>6, c2=i&63;
    float2 v = gs[(size_t)yy*32768 + c2];
    float* d = U + ((yy>>3)*4+(yy&3))*264 + ((yy>>2)&1);
    d[(2*c2)*2]=tf32f(v.x); d[(2*c2+1)*2]=tf32f(v.y);
  }
  __syncthreads();
  int warp=tid>>5, lane=tid&31, qid=lane>>2, rid=lane&3;
  // GEMM1 fwd-H: M=32,K=64,N=128
  float4 C1[2][2][2];
#pragma unroll
  for (int a=0;a<2;a++)
#pragma unroll
    for (int m=0;m<2;m++)
#pragma unroll
      for (int n=0;n<2;n++) C1[a][m][n] = make_float4(0.f,0.f,0.f,0.f);
#pragma unroll
  for (int kk=0; kk<8; kk++){
    const float* Bp = U + (kk*4+rid)*264;
    float2 bf0 = *(const float2*)(Bp + (warp*16+qid)*2);
    float2 bf1 = *(const float2*)(Bp + (warp*16+8+qid)*2);
#pragma unroll
    for (int mat=0; mat<2; mat++){
      const float* Ap = sA_W + (mat*8+kk)*256;
#pragma unroll
      for (int mt=0; mt<2; mt++){
        float2 a02 = *(const float2*)(Ap + (mt*16+qid)*8 + rid*2);
        float2 a13 = *(const float2*)(Ap + (mt*16+qid+8)*8 + rid*2);
        mma8(C1[mat][mt][0], a02.x,a13.x,a02.y,a13.y, bf0.x, bf0.y);
        mma8(C1[mat][mt][1], a02.x,a13.x,a02.y,a13.y, bf1.x, bf1.y);
      }
    }
  }
  __syncthreads();
  float2* sSpec = (float2*)U;   // stride 65
#pragma unroll
  for (int mt=0; mt<2; mt++)
#pragma unroll
    for (int nt=0; nt<2; nt++){
      float4 cc = C1[0][mt][nt], cs = C1[1][mt][nt];
      int c2 = warp*8+nt*4+rid, h0 = mt*16+qid;
      sSpec[h0*65 + c2]     = make_float2(cc.x+cs.y, cc.y-cs.x);
      sSpec[(h0+8)*65 + c2] = make_float2(cc.z+cs.w, cc.w-cs.z);
    }
  __syncthreads();
  // MLP: inst=(nb0,h), 2 threads each (half)
  {
    int inst=tid>>1, half=tid&1, nb0=inst>>5, h=inst&31;
    const float* W1R = sW + nb0*256;
    const float* W1I = sW + (4+nb0)*256;
    const float* W2R = sW + (8+nb0)*256;
    const float* W2I = sW + (12+nb0)*256;
    const float* Bb0 = sBias + nb0*17;
    const float* Bb1 = sBias + (4+nb0)*17;
    const float* Bb2 = sBias + (8+nb0)*17;
    const float* Bb3 = sBias + (12+nb0)*17;
    float xr[16], xi[16];
#pragma unroll
    for (int i=0;i<16;i++){ float2 v = sSpec[h*65 + nb0*16 + i]; xr[i]=v.x; xi[i]=v.y; }
    float pr[16], pi[16];
#pragma unroll
    for (int o=0;o<16;o++){ pr[o]=Bb0[o]; pi[o]=Bb1[o]; }
#pragma unroll
    for (int i=0;i<16;i++){
#pragma unroll
      for (int o=0;o<16;o++){
        float wr = W1R[i*16+o], wi = W1I[i*16+o];
        pr[o] += xr[i]*wr - xi[i]*wi;
        pi[o] += xi[i]*wr + xr[i]*wi;
      }
    }
#pragma unroll
    for (int o=0;o<16;o++){ pr[o]=gelu_f(pr[o]); pi[o]=gelu_f(pi[o]); }
    float qr[8], qi[8];
#pragma unroll
    for (int oo=0;oo<8;oo++){ int o=half*8+oo; qr[oo]=Bb2[o]; qi[oo]=Bb3[o]; }
#pragma unroll
    for (int i=0;i<16;i++){
#pragma unroll
      for (int oo=0;oo<8;oo++){
        int o=half*8+oo;
        float wr = W2R[i*16+o], wi = W2I[i*16+o];
        qr[oo] += pr[i]*wr - pi[i]*wi;
        qi[oo] += pi[i]*wr + pr[i]*wi;
      }
    }
    float* d = U2 + ((h>>3)*4+(h&3))*264 + ((h>>2)&1);
#pragma unroll
    for (int oo=0;oo<8;oo++){
      int c2o = nb0*16 + half*8 + oo;
      d[(2*c2o  )*2] = tf32f(qr[oo]);
      d[(2*c2o+1)*2] = tf32f(qi[oo]);
    }
  }
  __syncthreads();
  // GEMM2 inv-H: M=64,K=32,N=128
  float4 C3[2][4][2];
#pragma unroll
  for (int a=0;a<2;a++)
#pragma unroll
    for (int m=0;m<4;m++)
#pragma unroll
      for (int n=0;n<2;n++) C3[a][m][n] = make_float4(0.f,0.f,0.f,0.f);
#pragma unroll
  for (int kk=0; kk<4; kk++){
    const float* Bp = U2 + (kk*4+rid)*264;
    float2 bf0 = *(const float2*)(Bp + (warp*16+qid)*2);
    float2 bf1 = *(const float2*)(Bp + (warp*16+8+qid)*2);
#pragma unroll
    for (int mat=0; mat<2; mat++){
      const float* Ap = sA_Wi + (mat*4+kk)*512;
#pragma unroll
      for (int mt=0; mt<4; mt++){
        float2 a02 = *(const float2*)(Ap + (mt*16+qid)*8 + rid*2);
        float2 a13 = *(const float2*)(Ap + (mt*16+qid+8)*8 + rid*2);
        mma8(C3[mat][mt][0], a02.x,a13.x,a02.y,a13.y, bf0.x, bf0.y);
        mma8(C3[mat][mt][1], a02.x,a13.x,a02.y,a13.y, bf1.x, bf1.y);
      }
    }
  }
#pragma unroll
  for (int mt=0; mt<4; mt++)
#pragma unroll
    for (int nt=0; nt<2; nt++){
      float4 cc = C3[0][mt][nt], cs = C3[1][mt][nt];
      int c2 = warp*8+nt*4+rid, y0 = mt*16+qid;
      gs[(size_t)y0*32768 + c2]     = make_float2(cc.x-cs.y, cc.y+cs.x);
      gs[(size_t)(y0+8)*32768 + c2] = make_float2(cc.z-cs.w, cc.w+cs.z);
    }
}

// ================= K3: fused inverse (inv-W GEMM + inv-L GEMM + residual) =================
// grid (ct=16, y=64, b=4), 256 thr.
__global__ void __launch_bounds__(256) k_inv(const float* __restrict__ x, float* __restrict__ out){
  extern __shared__ float sm[];
  float* sA_Wi = sm;           // 4096
  float* sA_Li = sm + 4096;    // 512
  float* V     = sm + 4608;    // 4224 (B1i 16x264)
  float* V2    = sm + 8832;    // 8256 (B2i 8x1032)
  int tid = threadIdx.x;
  int ct = blockIdx.x, y = blockIdx.y, b = blockIdx.z;
  for (int i=tid; i<1024; i+=256) ((float4*)sA_Wi)[i] = ((const float4*)g_TA_Wi)[i];
  for (int i=tid; i<128;  i+=256) ((float4*)sA_Li)[i] = ((const float4*)g_TA_Li)[i];
  const float2* gs = g_s2 + (size_t)(b*64+y)*32768 + ct*8;
  for (int i=tid; i<2048; i+=256){
    int w=i>>6, l=(i>>3)&7, c=i&7;
    float2 v = gs[(size_t)w*1024 + l*128 + c];
    float* d = V + ((w>>3)*4+(w&3))*264 + ((w>>2)&1);
    int n=(l*8+c)*2;
    d[n*2]=tf32f(v.x); d[(n+1)*2]=tf32f(v.y);
  }
  __syncthreads();
  int warp=tid>>5, lane=tid&31, qid=lane>>2, rid=lane&3;
  // GEMM1 inv-W: M=64,K=32,N=128
  float4 C1[2][4][2];
#pragma unroll
  for (int a=0;a<2;a++)
#pragma unroll
    for (int m=0;m<4;m++)
#pragma unroll
      for (int n=0;n<2;n++) C1[a][m][n] = make_float4(0.f,0.f,0.f,0.f);
#pragma unroll
  for (int kk=0; kk<4; kk++){
    const float* Bp = V + (kk*4+rid)*264;
    float2 bf0 = *(const float2*)(Bp + (warp*16+qid)*2);
    float2 bf1 = *(const float2*)(Bp + (warp*16+8+qid)*2);
#pragma unroll
    for (int mat=0; mat<2; mat++){
      const float* Ap = sA_Wi + (mat*4+kk)*512;
#pragma unroll
      for (int mt=0; mt<4; mt++){
        float2 a02 = *(const float2*)(Ap + (mt*16+qid)*8 + rid*2);
        float2 a13 = *(const float2*)(Ap + (mt*16+qid+8)*8 + rid*2);
        mma8(C1[mat][mt][0], a02.x,a13.x,a02.y,a13.y, bf0.x, bf0.y);
        mma8(C1[mat][mt][1], a02.x,a13.x,a02.y,a13.y, bf1.x, bf1.y);
      }
    }
  }
  // combine + scatter to B2i[k2=2l+pp][n1=xx*8+c] (V2 disjoint from V: no barrier needed yet)
#pragma unroll
  for (int mt=0; mt<4; mt++)
#pragma unroll
    for (int nt=0; nt<2; nt++){
      float4 cc = C1[0][mt][nt], cs = C1[1][mt][nt];
      int lc = warp*8+nt*4+rid, l=lc>>3, c=lc&7;
      int xx0 = mt*16+qid;
      int k2r = 2*l, k2i = 2*l+1;
      float* dr = V2 + ((k2r>>3)*4+(k2r&3))*1032 + ((k2r>>2)&1);
      float* di = V2 + ((k2i>>3)*4+(k2i&3))*1032 + ((k2i>>2)&1);
      dr[(xx0*8+c)*2]     = tf32f(cc.x - cs.y);
      di[(xx0*8+c)*2]     = tf32f(cc.y + cs.x);
      dr[((xx0+8)*8+c)*2] = tf32f(cc.z - cs.w);
      di[((xx0+8)*8+c)*2] = tf32f(cc.w + cs.z);
    }
  __syncthreads();
  // GEMM2 inv-L: M=32,K=16,N=512 (real output)
  float4 C2[2][8];
#pragma unroll
  for (int m=0;m<2;m++)
#pragma unroll
    for (int n=0;n<8;n++) C2[m][n] = make_float4(0.f,0.f,0.f,0.f);
#pragma unroll
  for (int kk=0; kk<2; kk++){
    const float* Ap = sA_Li + kk*256;
    float2 a02[2], a13[2];
#pragma unroll
    for (int mt=0; mt<2; mt++){
      a02[mt] = *(const float2*)(Ap + (mt*16+qid)*8 + rid*2);
      a13[mt] = *(const float2*)(Ap + (mt*16+qid+8)*8 + rid*2);
    }
    const float* Bp = V2 + (kk*4+rid)*1032;
#pragma unroll
    for (int nt=0; nt<8; nt++){
      float2 bf = *(const float2*)(Bp + (warp*64+nt*8+qid)*2);
#pragma unroll
      for (int mt=0; mt<2; mt++)
        mma8(C2[mt][nt], a02[mt].x, a13[mt].x, a02[mt].y, a13[mt].y, bf.x, bf.y);
    }
  }
  // epilogue: + residual, write output
  const float* xb = x + (size_t)(b*64+y)*262144 + ct*8;
  float* ob = out + (size_t)(b*64+y)*262144 + ct*8;
#pragma unroll
  for (int mt=0; mt<2; mt++)
#pragma unroll
    for (int nt=0; nt<8; nt++){
      float4 cv = C2[mt][nt];
      int n1 = warp*64+nt*8+rid*2, xx=n1>>3, c=n1&7;
      int t0 = mt*16+qid;
      size_t a0 = (size_t)xx*4096 + t0*128 + c;
      size_t a1 = (size_t)xx*4096 + (t0+8)*128 + c;
      float2 r0 = *(const float2*)(xb + a0);
      float2 r1 = *(const float2*)(xb + a1);
      *(float2*)(ob + a0) = make_float2(cv.x + r0.x, cv.y + r0.y);
      *(float2*)(ob + a1) = make_float2(cv.z + r1.x, cv.w + r1.y);
    }
}

// ---------------- launch ----------------
extern "C" void kernel_launch(void* const* d_in, const int* in_sizes, int n_in,
                              void* d_out, int out_size){
  (void)in_sizes; (void)n_in; (void)out_size;
  const float* x = (const float*)d_in[0];
  cudaFuncSetAttribute(k_fwd, cudaFuncAttributeMaxDynamicSharedMemorySize, 84480);
  cudaFuncSetAttribute(k_mid, cudaFuncAttributeMaxDynamicSharedMemorySize, 100928);
  cudaFuncSetAttribute(k_inv, cudaFuncAttributeMaxDynamicSharedMemorySize, 68352);
  k_prep<<<8,256>>>((const float*)d_in[1], (const float*)d_in[2], (const float*)d_in[3],
                    (const float*)d_in[4], (const float*)d_in[5], (const float*)d_in[6],
                    (const float*)d_in[7], (const float*)d_in[8], (const float*)d_in[9],
                    (const float*)d_in[10], (const float*)d_in[11], (const float*)d_in[12],
                    (const float*)d_in[13]);
  k_init_T<<<36,256>>>();
  k_fwd<<<dim3(16,64,4),256,84480>>>(x);
  k_mid<<<dim3(512,4),256,100928>>>();
  k_inv<<<dim3(16,64,4),256,68352>>>(x, (float*)d_out);
}

// round 7
// speedup vs baseline: 1.2429x; 1.2429x over previous
#include <cuda_runtime.h>
#include <math.h>

// ---------------- scratch ----------------
__device__ __align__(16) float2 g_s3[16777216];  // [4][64][64][8][128] fwd-L out / inv-W out
__device__ __align__(16) float2 g_s2[8388608];   // [4][64][32][8][128] workspace (k_mid in-place)
__device__ __align__(16) float  g_W[8192];       // [4 mats][8 blk][16][16] folded MLP weights
__device__ __align__(16) float  g_Bias[512];     // [4][8][16] folded biases
// per-lane packed tf32 mma A-fragments: idx = ((mat*KT+kk)*MT+mt)*32+lane, f4=(a0,a1,a2,a3)
__device__ __align__(16) float4 g_A4W[1024];     // fwd W/H: M=32,K=64 (cos|sin), 1/8 baked
__device__ __align__(16) float4 g_A4Wi[1024];    // inv W/H: M=64,K=32 (cos|sin), 1/8 baked

__constant__ float2 TW32[32] = {
  { 1.000000000f, 0.000000000f},{ 0.980785280f, 0.195090322f},{ 0.923879533f, 0.382683432f},{ 0.831469612f, 0.555570233f},
  { 0.707106781f, 0.707106781f},{ 0.555570233f, 0.831469612f},{ 0.382683432f, 0.923879533f},{ 0.195090322f, 0.980785280f},
  { 0.000000000f, 1.000000000f},{-0.195090322f, 0.980785280f},{-0.382683432f, 0.923879533f},{-0.555570233f, 0.831469612f},
  {-0.707106781f, 0.707106781f},{-0.831469612f, 0.555570233f},{-0.923879533f, 0.382683432f},{-0.980785280f, 0.195090322f},
  {-1.000000000f, 0.000000000f},{-0.980785280f,-0.195090322f},{-0.923879533f,-0.382683432f},{-0.831469612f,-0.555570233f},
  {-0.707106781f,-0.707106781f},{-0.555570233f,-0.831469612f},{-0.382683432f,-0.923879533f},{-0.195090322f,-0.980785280f},
  { 0.000000000f,-1.000000000f},{ 0.195090322f,-0.980785280f},{ 0.382683432f,-0.923879533f},{ 0.555570233f,-0.831469612f},
  { 0.707106781f,-0.707106781f},{ 0.831469612f,-0.555570233f},{ 0.923879533f,-0.382683432f},{ 0.980785280f,-0.195090322f}
};

__device__ __forceinline__ float gelu_f(float v){
  return 0.5f*v*(1.0f+erff(v*0.7071067811865476f));
}
__device__ __forceinline__ float tf32f(float f){
  unsigned u; asm("cvt.rna.tf32.f32 %0, %1;" : "=r"(u) : "f"(f));
  return __uint_as_float(u);
}
__device__ __forceinline__ void mma8(float4& d, float a0, float a1, float a2, float a3,
                                     float b0, float b1){
  asm volatile("mma.sync.aligned.m16n8k8.row.col.f32.tf32.tf32.f32 "
    "{%0,%1,%2,%3}, {%4,%5,%6,%7}, {%8,%9}, {%0,%1,%2,%3};"
    : "+f"(d.x), "+f"(d.y), "+f"(d.z), "+f"(d.w)
    : "r"(__float_as_uint(a0)), "r"(__float_as_uint(a1)),
      "r"(__float_as_uint(a2)), "r"(__float_as_uint(a3)),
      "r"(__float_as_uint(b0)), "r"(__float_as_uint(b1)));
}

// ---------------- K0a: build packed twiddle fragments ----------------
__device__ __forceinline__ float twval(int mat, int m, int k){
  double a = (double)(m*k)/32.0;   // angle = pi * m*k/32 = 2pi*m*k/64
  return tf32f((float)((mat ? sinpi(a) : cospi(a))*0.125));
}
__global__ void k_init4(){
  int e = blockIdx.x*256 + threadIdx.x;   // 0..2047
  int lane = e&31, qid = lane>>2, rid = lane&3;
  int which = e>>10, j = e&1023;
  if (which==0){                           // fwd: MT=2, KT=8
    int mt=(j>>5)&1, kk=(j>>6)&7, mat=j>>9;
    int r0=mt*16+qid, r1=r0+8, k0=kk*8+rid, k1=k0+4;
    g_A4W[j] = make_float4(twval(mat,r0,k0), twval(mat,r1,k0),
                           twval(mat,r0,k1), twval(mat,r1,k1));
  } else {                                 // inv: MT=4, KT=4
    int mt=(j>>5)&3, kk=(j>>7)&3, mat=j>>9;
    int r0=mt*16+qid, r1=r0+8, k0=kk*8+rid, k1=k0+4;
    g_A4Wi[j] = make_float4(twval(mat,r0,k0), twval(mat,r1,k0),
                            twval(mat,r0,k1), twval(mat,r1,k1));
  }
}

// ---------------- K0: fold HydraLoRA ----------------
__global__ void k_prep(const float* __restrict__ w1, const float* __restrict__ b1,
                       const float* __restrict__ w2, const float* __restrict__ b2,
                       const float* __restrict__ A1r, const float* __restrict__ B1r,
                       const float* __restrict__ A1i, const float* __restrict__ B1i,
                       const float* __restrict__ A2r, const float* __restrict__ B2r,
                       const float* __restrict__ A2i, const float* __restrict__ B2i,
                       const float* __restrict__ ew){
  int k  = blockIdx.x;
  int io = threadIdx.x;
  int i = io >> 4, o = io & 15;
  float e0 = ew[0], e1 = ew[1], e2 = ew[2], e3 = ew[3];
  const float s = 0.03125f;
  const float* Ws[4] = { w1 + k*256, w1 + 2048 + k*256, w2 + k*256, w2 + 2048 + k*256 };
  const float* As[4] = { A1r + k*512, A1i + k*512, A2r + k*512, A2i + k*512 };
  const float* Bs[4] = { B1r + k*2048, B1i + k*2048, B2r + k*2048, B2i + k*2048 };
#pragma unroll
  for (int m = 0; m < 4; m++){
    const float* A  = As[m] + i*32;
    const float* Bb = Bs[m];
    float acc = 0.f;
    for (int r = 0; r < 32; r++){
      float bm = e0*Bb[r*16+o] + e1*Bb[512+r*16+o] + e2*Bb[1024+r*16+o] + e3*Bb[1536+r*16+o];
      acc = fmaf(A[r], bm, acc);
    }
    g_W[((m*8+k)*16+i)*16+o] = Ws[m][i*16+o] + s*acc;
  }
  if (io < 16){
    float b10 = b1[k*16+io], b11 = b1[128+k*16+io];
    float b20 = b2[k*16+io], b21 = b2[128+k*16+io];
    g_Bias[      k*16+io] = b10 - b11;
    g_Bias[128 + k*16+io] = b10 + b11;
    g_Bias[256 + k*16+io] = b20 - b21;
    g_Bias[384 + k*16+io] = b20 + b21;
  }
}

// ---------------- K1: forward rfft over L (radix-2 split) ----------------
__global__ void k_fwd_l(const float* __restrict__ x){
  __shared__ float2 tw[32];
  if (threadIdx.x < 32) tw[threadIdx.x] = TW32[threadIdx.x];
  __syncthreads();
  int site = blockIdx.x;      // b*4096 + y*64 + xx
  int c = threadIdx.x;
  const float* xp = x + (size_t)site*4096 + c;
  float u[16], dd[16];
#pragma unroll
  for (int t=0;t<16;t++){
    float a = xp[t*128], b = xp[(t+16)*128];
    u[t] = a + b; dd[t] = a - b;
  }
  float ar[8], ai[8];
#pragma unroll
  for (int l=0;l<8;l++){ ar[l]=0.f; ai[l]=0.f; }
#pragma unroll
  for (int t=0;t<16;t++){
#pragma unroll
    for (int j=0;j<4;j++){
      float2 we = tw[(t*2*j)&31];          // even l = 2j : uses u
      ar[2*j]   = fmaf( u[t], we.x, ar[2*j]);
      ai[2*j]   = fmaf(-u[t], we.y, ai[2*j]);
      float2 wo = tw[(t*(2*j+1))&31];      // odd l = 2j+1 : uses d
      ar[2*j+1] = fmaf( dd[t], wo.x, ar[2*j+1]);
      ai[2*j+1] = fmaf(-dd[t], wo.y, ai[2*j+1]);
    }
  }
  const float s = 0.1767766952966369f; // 1/sqrt(32)
  float2* op = g_s3 + (size_t)site*1024 + c;
#pragma unroll
  for (int l=0;l<8;l++) op[l*128] = make_float2(ar[l]*s, ai[l]*s);
}

// ---------------- complex DFT GEMM stage (A via __ldg fragments) ----------------
template<int M, int K, int SGN>
__global__ void __launch_bounds__(128) k_dft_mma(const float* __restrict__ in,
                                                 float* __restrict__ out,
                                                 const float4* __restrict__ A4,
                                                 int rowLen2, size_t inStride2,
                                                 size_t outStride2){
  constexpr int KT = K/8;
  constexpr int MT = M/16;
  constexpr int BSLICE = 136;
  __shared__ float Bs[KT*4*BSLICE];
  int tid = threadIdx.x;
  {
    const float* src = in + (size_t)blockIdx.y*inStride2 + blockIdx.x*64;
    for (int i = tid; i < K*16; i += 128){
      int k = i >> 4, c4 = (i & 15)*4;
      float4 v = *(const float4*)(src + (size_t)k*rowLen2 + c4);
      float* d = Bs + ((k>>3)*4 + (k&3))*BSLICE + ((k>>2)&1);
      d[(c4+0)*2] = tf32f(v.x);
      d[(c4+1)*2] = tf32f(v.y);
      d[(c4+2)*2] = tf32f(v.z);
      d[(c4+3)*2] = tf32f(v.w);
    }
  }
  __syncthreads();
  int warp = tid>>5, lane = tid&31;
  int qid = lane>>2, rid = lane&3;
  int wcol = warp*16;
  float4 C[2][MT][2];
#pragma unroll
  for (int a=0;a<2;a++)
#pragma unroll
    for (int b=0;b<MT;b++)
#pragma unroll
      for (int c=0;c<2;c++) C[a][b][c] = make_float4(0.f,0.f,0.f,0.f);
#pragma unroll
  for (int kk=0; kk<KT; kk++){
    float2 Bf[2];
#pragma unroll
    for (int nt=0; nt<2; nt++)
      Bf[nt] = *(const float2*)(Bs + (kk*4 + rid)*BSLICE + (wcol + nt*8 + qid)*2);
#pragma unroll
    for (int mm=0; mm<2; mm++){
#pragma unroll
      for (int mt=0; mt<MT; mt++){
        float4 af = __ldg(A4 + ((mm*KT+kk)*MT+mt)*32 + lane);
#pragma unroll
        for (int nt=0; nt<2; nt++)
          mma8(C[mm][mt][nt], af.x, af.y, af.z, af.w, Bf[nt].x, Bf[nt].y);
      }
    }
  }
  float* ob = out + (size_t)blockIdx.y*outStride2 + blockIdx.x*64;
#pragma unroll
  for (int mt=0; mt<MT; mt++){
#pragma unroll
    for (int nt=0; nt<2; nt++){
      float4 cr = C[0][mt][nt], ci = C[1][mt][nt];
      int col = wcol + nt*8 + rid*2;
      int m0 = mt*16 + qid;
      float2 v0, v1;
      if (SGN > 0){
        v0 = make_float2(cr.x + ci.y, cr.y - ci.x);
        v1 = make_float2(cr.z + ci.w, cr.w - ci.z);
      } else {
        v0 = make_float2(cr.x - ci.y, cr.y + ci.x);
        v1 = make_float2(cr.z - ci.w, cr.w + ci.z);
      }
      *(float2*)(ob + (size_t)m0*rowLen2 + col) = v0;
      *(float2*)(ob + (size_t)(m0+8)*rowLen2 + col) = v1;
    }
  }
}

// ---------------- K_mid: fwd-H + MLP + inv-H in place ----------------
// grid (512 = w*16+l*2+chalf, b=4), 256 thr.
// smem floats: sW[4096]@0 | sBias[272]@4096 | U[8448]@4368 | U2[4224]@12816 = 68160 B
__global__ void __launch_bounds__(256,3) k_mid(){
  extern __shared__ float sm[];
  float* sW    = sm;
  float* sBias = sm + 4096;
  float* U     = sm + 4368;
  float* U2    = sm + 12816;
  int tid = threadIdx.x;
  int bx = blockIdx.x, b = blockIdx.y;
  int w = bx>>4, l = (bx>>1)&7, chalf = bx&1;
  for (int i=tid; i<1024; i+=256){
    int mg=i>>8, nb0=(i>>6)&3;
    ((float4*)sW)[i] = ((const float4*)g_W)[(mg*8+chalf*4+nb0)*64 + (i&63)];
  }
  { int mg=tid>>6, nb0=(tid>>4)&3, o=tid&15;
    sBias[(mg*4+nb0)*17+o] = g_Bias[mg*128 + (chalf*4+nb0)*16 + o]; }
  float2* gs = g_s2 + (size_t)b*2097152 + (size_t)w*1024 + l*128 + chalf*64;
  for (int i=tid; i<4096; i+=256){
    int yy=i>>6, c2=i&63;
    float2 v = gs[(size_t)yy*32768 + c2];
    float* d = U + ((yy>>3)*4+(yy&3))*264 + ((yy>>2)&1);
    d[(2*c2)*2]=tf32f(v.x); d[(2*c2+1)*2]=tf32f(v.y);
  }
  __syncthreads();
  int warp=tid>>5, lane=tid&31, qid=lane>>2, rid=lane&3;
  // GEMM1 fwd-H: M=32,K=64,N=128
  float4 C1[2][2][2];
#pragma unroll
  for (int a=0;a<2;a++)
#pragma unroll
    for (int m=0;m<2;m++)
#pragma unroll
      for (int n=0;n<2;n++) C1[a][m][n] = make_float4(0.f,0.f,0.f,0.f);
#pragma unroll
  for (int kk=0; kk<8; kk++){
    const float* Bp = U + (kk*4+rid)*264;
    float2 bf0 = *(const float2*)(Bp + (warp*16+qid)*2);
    float2 bf1 = *(const float2*)(Bp + (warp*16+8+qid)*2);
#pragma unroll
    for (int mat=0; mat<2; mat++){
#pragma unroll
      for (int mt=0; mt<2; mt++){
        float4 af = __ldg(&g_A4W[((mat*8+kk)*2+mt)*32 + lane]);
        mma8(C1[mat][mt][0], af.x,af.y,af.z,af.w, bf0.x, bf0.y);
        mma8(C1[mat][mt][1], af.x,af.y,af.z,af.w, bf1.x, bf1.y);
      }
    }
  }
  __syncthreads();
  float2* sSpec = (float2*)U;   // stride 65
#pragma unroll
  for (int mt=0; mt<2; mt++)
#pragma unroll
    for (int nt=0; nt<2; nt++){
      float4 cc = C1[0][mt][nt], cs = C1[1][mt][nt];
      int c2 = warp*8+nt*4+rid, h0 = mt*16+qid;
      sSpec[h0*65 + c2]     = make_float2(cc.x+cs.y, cc.y-cs.x);
      sSpec[(h0+8)*65 + c2] = make_float2(cc.z+cs.w, cc.w-cs.z);
    }
  __syncthreads();
  // MLP: inst=(nb0,h), 2 threads each (half); float4 weight broadcasts
  {
    int inst=tid>>1, half=tid&1, nb0=inst>>5, h=inst&31;
    const float* W1R = sW + nb0*256;
    const float* W1I = sW + (4+nb0)*256;
    const float* W2R = sW + (8+nb0)*256;
    const float* W2I = sW + (12+nb0)*256;
    const float* Bb0 = sBias + nb0*17;
    const float* Bb1 = sBias + (4+nb0)*17;
    const float* Bb2 = sBias + (8+nb0)*17;
    const float* Bb3 = sBias + (12+nb0)*17;
    float xr[16], xi[16];
#pragma unroll
    for (int i=0;i<16;i++){ float2 v = sSpec[h*65 + nb0*16 + i]; xr[i]=v.x; xi[i]=v.y; }
    float pr[16], pi[16];
#pragma unroll
    for (int o=0;o<16;o++){ pr[o]=Bb0[o]; pi[o]=Bb1[o]; }
#pragma unroll
    for (int i=0;i<16;i++){
      float xrv = xr[i], xiv = xi[i];
#pragma unroll
      for (int o4=0;o4<4;o4++){
        float4 wr = *(const float4*)(W1R + i*16 + o4*4);
        float4 wi = *(const float4*)(W1I + i*16 + o4*4);
        pr[o4*4+0] += xrv*wr.x - xiv*wi.x;  pi[o4*4+0] += xiv*wr.x + xrv*wi.x;
        pr[o4*4+1] += xrv*wr.y - xiv*wi.y;  pi[o4*4+1] += xiv*wr.y + xrv*wi.y;
        pr[o4*4+2] += xrv*wr.z - xiv*wi.z;  pi[o4*4+2] += xiv*wr.z + xrv*wi.z;
        pr[o4*4+3] += xrv*wr.w - xiv*wi.w;  pi[o4*4+3] += xiv*wr.w + xrv*wi.w;
      }
    }
#pragma unroll
    for (int o=0;o<16;o++){ pr[o]=gelu_f(pr[o]); pi[o]=gelu_f(pi[o]); }
    float qr[8], qi[8];
#pragma unroll
    for (int oo=0;oo<8;oo++){ int o=half*8+oo; qr[oo]=Bb2[o]; qi[oo]=Bb3[o]; }
#pragma unroll
    for (int i=0;i<16;i++){
      float prv = pr[i], piv = pi[i];
#pragma unroll
      for (int o4=0;o4<2;o4++){
        float4 wr = *(const float4*)(W2R + i*16 + half*8 + o4*4);
        float4 wi = *(const float4*)(W2I + i*16 + half*8 + o4*4);
        qr[o4*4+0] += prv*wr.x - piv*wi.x;  qi[o4*4+0] += piv*wr.x + prv*wi.x;
        qr[o4*4+1] += prv*wr.y - piv*wi.y;  qi[o4*4+1] += piv*wr.y + prv*wi.y;
        qr[o4*4+2] += prv*wr.z - piv*wi.z;  qi[o4*4+2] += piv*wr.z + prv*wi.z;
        qr[o4*4+3] += prv*wr.w - piv*wi.w;  qi[o4*4+3] += piv*wr.w + prv*wi.w;
      }
    }
    float* d = U2 + ((h>>3)*4+(h&3))*264 + ((h>>2)&1);
#pragma unroll
    for (int oo=0;oo<8;oo++){
      int c2o = nb0*16 + half*8 + oo;
      d[(2*c2o  )*2] = tf32f(qr[oo]);
      d[(2*c2o+1)*2] = tf32f(qi[oo]);
    }
  }
  __syncthreads();
  // GEMM2 inv-H: M=64,K=32,N=128
  float4 C3[2][4][2];
#pragma unroll
  for (int a=0;a<2;a++)
#pragma unroll
    for (int m=0;m<4;m++)
#pragma unroll
      for (int n=0;n<2;n++) C3[a][m][n] = make_float4(0.f,0.f,0.f,0.f);
#pragma unroll
  for (int kk=0; kk<4; kk++){
    const float* Bp = U2 + (kk*4+rid)*264;
    float2 bf0 = *(const float2*)(Bp + (warp*16+qid)*2);
    float2 bf1 = *(const float2*)(Bp + (warp*16+8+qid)*2);
#pragma unroll
    for (int mat=0; mat<2; mat++){
#pragma unroll
      for (int mt=0; mt<4; mt++){
        float4 af = __ldg(&g_A4Wi[((mat*4+kk)*4+mt)*32 + lane]);
        mma8(C3[mat][mt][0], af.x,af.y,af.z,af.w, bf0.x, bf0.y);
        mma8(C3[mat][mt][1], af.x,af.y,af.z,af.w, bf1.x, bf1.y);
      }
    }
  }
#pragma unroll
  for (int mt=0; mt<4; mt++)
#pragma unroll
    for (int nt=0; nt<2; nt++){
      float4 cc = C3[0][mt][nt], cs = C3[1][mt][nt];
      int c2 = warp*8+nt*4+rid, y0 = mt*16+qid;
      gs[(size_t)y0*32768 + c2]     = make_float2(cc.x-cs.y, cc.y+cs.x);
      gs[(size_t)(y0+8)*32768 + c2] = make_float2(cc.z-cs.w, cc.w+cs.z);
    }
}

// ---------------- K7: inverse rfft over L (radix-2) + residual ----------------
__global__ void k_inv_l(const float* __restrict__ xin, float* __restrict__ out){
  __shared__ float2 tw[32];
  if (threadIdx.x < 32) tw[threadIdx.x] = TW32[threadIdx.x];
  __syncthreads();
  int tid = blockIdx.x*blockDim.x + threadIdx.x;
  int c = tid & 127;
  int site = tid >> 7;
  const float2* ip = g_s3 + (size_t)site*1024 + c;
  float Xr[8], Xi[8];
#pragma unroll
  for (int l=0;l<8;l++){ float2 v = ip[l*128]; Xr[l]=v.x; Xi[l]=v.y; }
#pragma unroll
  for (int l=1;l<8;l++){ Xr[l]*=2.f; Xi[l]*=2.f; }
  const float s = 0.1767766952966369f;
  const float* rp = xin + (size_t)site*4096 + c;
  float* op = out + (size_t)site*4096 + c;
#pragma unroll
  for (int t=0;t<16;t++){
    float E = Xr[0];
    float O = 0.f;
#pragma unroll
    for (int j=1;j<4;j++){
      float2 we = tw[(2*j*t)&31];
      E += Xr[2*j]*we.x - Xi[2*j]*we.y;
    }
#pragma unroll
    for (int j=0;j<4;j++){
      float2 wo = tw[((2*j+1)*t)&31];
      O += Xr[2*j+1]*wo.x - Xi[2*j+1]*wo.y;
    }
    op[t*128]      = fmaf(E+O, s, rp[t*128]);
    op[(t+16)*128] = fmaf(E-O, s, rp[(t+16)*128]);
  }
}

// ---------------- launch ----------------
extern "C" void kernel_launch(void* const* d_in, const int* in_sizes, int n_in,
                              void* d_out, int out_size){
  (void)in_sizes; (void)n_in; (void)out_size;
  const float* x = (const float*)d_in[0];
  void *ps3, *ps2, *paw, *pawi;
  cudaGetSymbolAddress(&ps3,  g_s3);
  cudaGetSymbolAddress(&ps2,  g_s2);
  cudaGetSymbolAddress(&paw,  g_A4W);
  cudaGetSymbolAddress(&pawi, g_A4Wi);
  const float* s3 = (const float*)ps3;
  const float* s2 = (const float*)ps2;
  const float4* aw  = (const float4*)paw;
  const float4* awi = (const float4*)pawi;
  cudaFuncSetAttribute(k_mid, cudaFuncAttributeMaxDynamicSharedMemorySize, 68160);

  k_prep<<<8,256>>>((const float*)d_in[1], (const float*)d_in[2], (const float*)d_in[3],
                    (const float*)d_in[4], (const float*)d_in[5], (const float*)d_in[6],
                    (const float*)d_in[7], (const float*)d_in[8], (const float*)d_in[9],
                    (const float*)d_in[10], (const float*)d_in[11], (const float*)d_in[12],
                    (const float*)d_in[13]);
  k_init4<<<8,256>>>();
  k_fwd_l<<<16384,128>>>(x);
  // fwd W: Out[32][1024c] = T @ In[64][1024c], 256 (b,y) batches
  k_dft_mma<32,64, 1><<<dim3(32,256),128>>>(s3, (float*)s2, aw, 2048, 131072, 65536);
  // fwd H + MLP + inv H, in place on g_s2
  k_mid<<<dim3(512,4),256,68160>>>();
  // inv W: Out[64][1024c] = T @ In[32][1024c]
  k_dft_mma<64,32,-1><<<dim3(32,256),128>>>(s2, (float*)s3, awi, 2048, 65536, 131072);
  k_inv_l<<<16384,128>>>(x, (float*)d_out);
}

// round 8
// speedup vs baseline: 1.2834x; 1.0325x over previous
#include <cuda_runtime.h>
#include <math.h>

// ---------------- scratch ----------------
__device__ __align__(16) float2 g_s3[16777216];  // [4][64][64][8][128] fwd-L out / inv-W out
__device__ __align__(16) float2 g_s2[8388608];   // [4][64][32][8][128] workspace (k_mid in-place)
__device__ __align__(16) float  g_W[8192];       // [4 mats][8 blk][16][16] folded MLP weights
__device__ __align__(16) float  g_Bias[512];     // [4][8][16] folded biases
// per-lane packed tf32 mma A-fragments: idx = ((mat*KT+kk)*MT+mt)*32+lane
__device__ __align__(16) float4 g_A4W[1024];     // fwd W/H: M=32,K=64 (cos|sin), 1/8 baked
__device__ __align__(16) float4 g_A4Wi[1024];    // inv W/H: M=64,K=32 (cos|sin), 1/8 baked

__constant__ float2 TW32[32] = {
  { 1.000000000f, 0.000000000f},{ 0.980785280f, 0.195090322f},{ 0.923879533f, 0.382683432f},{ 0.831469612f, 0.555570233f},
  { 0.707106781f, 0.707106781f},{ 0.555570233f, 0.831469612f},{ 0.382683432f, 0.923879533f},{ 0.195090322f, 0.980785280f},
  { 0.000000000f, 1.000000000f},{-0.195090322f, 0.980785280f},{-0.382683432f, 0.923879533f},{-0.555570233f, 0.831469612f},
  {-0.707106781f, 0.707106781f},{-0.831469612f, 0.555570233f},{-0.923879533f, 0.382683432f},{-0.980785280f, 0.195090322f},
  {-1.000000000f, 0.000000000f},{-0.980785280f,-0.195090322f},{-0.923879533f,-0.382683432f},{-0.831469612f,-0.555570233f},
  {-0.707106781f,-0.707106781f},{-0.555570233f,-0.831469612f},{-0.382683432f,-0.923879533f},{-0.195090322f,-0.980785280f},
  { 0.000000000f,-1.000000000f},{ 0.195090322f,-0.980785280f},{ 0.382683432f,-0.923879533f},{ 0.555570233f,-0.831469612f},
  { 0.707106781f,-0.707106781f},{ 0.831469612f,-0.555570233f},{ 0.923879533f,-0.382683432f},{ 0.980785280f,-0.195090322f}
};

__device__ __forceinline__ float gelu_f(float v){
  return 0.5f*v*(1.0f+erff(v*0.7071067811865476f));
}
__device__ __forceinline__ float tf32f(float f){
  unsigned u; asm("cvt.rna.tf32.f32 %0, %1;" : "=r"(u) : "f"(f));
  return __uint_as_float(u);
}
__device__ __forceinline__ void mma8(float4& d, float a0, float a1, float a2, float a3,
                                     float b0, float b1){
  asm volatile("mma.sync.aligned.m16n8k8.row.col.f32.tf32.tf32.f32 "
    "{%0,%1,%2,%3}, {%4,%5,%6,%7}, {%8,%9}, {%0,%1,%2,%3};"
    : "+f"(d.x), "+f"(d.y), "+f"(d.z), "+f"(d.w)
    : "r"(__float_as_uint(a0)), "r"(__float_as_uint(a1)),
      "r"(__float_as_uint(a2)), "r"(__float_as_uint(a3)),
      "r"(__float_as_uint(b0)), "r"(__float_as_uint(b1)));
}

// ---------------- K0a: build packed twiddle fragments ----------------
__device__ __forceinline__ float twval(int mat, int m, int k){
  double a = (double)(m*k)/32.0;
  return tf32f((float)((mat ? sinpi(a) : cospi(a))*0.125));
}
__global__ void k_init4(){
  int e = blockIdx.x*256 + threadIdx.x;   // 0..2047
  int lane = e&31, qid = lane>>2, rid = lane&3;
  int which = e>>10, j = e&1023;
  if (which==0){                           // fwd: MT=2, KT=8
    int mt=(j>>5)&1, kk=(j>>6)&7, mat=j>>9;
    int r0=mt*16+qid, r1=r0+8, k0=kk*8+rid, k1=k0+4;
    g_A4W[j] = make_float4(twval(mat,r0,k0), twval(mat,r1,k0),
                           twval(mat,r0,k1), twval(mat,r1,k1));
  } else {                                 // inv: MT=4, KT=4
    int mt=(j>>5)&3, kk=(j>>7)&3, mat=j>>9;
    int r0=mt*16+qid, r1=r0+8, k0=kk*8+rid, k1=k0+4;
    g_A4Wi[j] = make_float4(twval(mat,r0,k0), twval(mat,r1,k0),
                            twval(mat,r0,k1), twval(mat,r1,k1));
  }
}

// ---------------- K0: fold HydraLoRA ----------------
__global__ void k_prep(const float* __restrict__ w1, const float* __restrict__ b1,
                       const float* __restrict__ w2, const float* __restrict__ b2,
                       const float* __restrict__ A1r, const float* __restrict__ B1r,
                       const float* __restrict__ A1i, const float* __restrict__ B1i,
                       const float* __restrict__ A2r, const float* __restrict__ B2r,
                       const float* __restrict__ A2i, const float* __restrict__ B2i,
                       const float* __restrict__ ew){
  int k  = blockIdx.x;
  int io = threadIdx.x;
  int i = io >> 4, o = io & 15;
  float e0 = ew[0], e1 = ew[1], e2 = ew[2], e3 = ew[3];
  const float s = 0.03125f;
  const float* Ws[4] = { w1 + k*256, w1 + 2048 + k*256, w2 + k*256, w2 + 2048 + k*256 };
  const float* As[4] = { A1r + k*512, A1i + k*512, A2r + k*512, A2i + k*512 };
  const float* Bs[4] = { B1r + k*2048, B1i + k*2048, B2r + k*2048, B2i + k*2048 };
#pragma unroll
  for (int m = 0; m < 4; m++){
    const float* A  = As[m] + i*32;
    const float* Bb = Bs[m];
    float acc = 0.f;
    for (int r = 0; r < 32; r++){
      float bm = e0*Bb[r*16+o] + e1*Bb[512+r*16+o] + e2*Bb[1024+r*16+o] + e3*Bb[1536+r*16+o];
      acc = fmaf(A[r], bm, acc);
    }
    g_W[((m*8+k)*16+i)*16+o] = Ws[m][i*16+o] + s*acc;
  }
  if (io < 16){
    float b10 = b1[k*16+io], b11 = b1[128+k*16+io];
    float b20 = b2[k*16+io], b21 = b2[128+k*16+io];
    g_Bias[      k*16+io] = b10 - b11;
    g_Bias[128 + k*16+io] = b10 + b11;
    g_Bias[256 + k*16+io] = b20 - b21;
    g_Bias[384 + k*16+io] = b20 + b21;
  }
}

// ---------------- K1: forward rfft over L (radix-2) ----------------
__global__ void k_fwd_l(const float* __restrict__ x){
  __shared__ float2 tw[32];
  if (threadIdx.x < 32) tw[threadIdx.x] = TW32[threadIdx.x];
  __syncthreads();
  int site = blockIdx.x;
  int c = threadIdx.x;
  const float* xp = x + (size_t)site*4096 + c;
  float u[16], dd[16];
#pragma unroll
  for (int t=0;t<16;t++){
    float a = xp[t*128], b = xp[(t+16)*128];
    u[t] = a + b; dd[t] = a - b;
  }
  float ar[8], ai[8];
#pragma unroll
  for (int l=0;l<8;l++){ ar[l]=0.f; ai[l]=0.f; }
#pragma unroll
  for (int t=0;t<16;t++){
#pragma unroll
    for (int j=0;j<4;j++){
      float2 we = tw[(t*2*j)&31];
      ar[2*j]   = fmaf( u[t], we.x, ar[2*j]);
      ai[2*j]   = fmaf(-u[t], we.y, ai[2*j]);
      float2 wo = tw[(t*(2*j+1))&31];
      ar[2*j+1] = fmaf( dd[t], wo.x, ar[2*j+1]);
      ai[2*j+1] = fmaf(-dd[t], wo.y, ai[2*j+1]);
    }
  }
  const float s = 0.1767766952966369f;
  float2* op = g_s3 + (size_t)site*1024 + c;
#pragma unroll
  for (int l=0;l<8;l++) op[l*128] = make_float2(ar[l]*s, ai[l]*s);
}

// ---------------- complex DFT GEMM stage (pair-split B layout) ----------------
// Bs[pair][slice][col]: pair=(k>>2)&1, slice=(k>>3)*4+(k&3), slice stride 72 (8-bank shift)
template<int M, int K, int SGN, int MINB>
__global__ void __launch_bounds__(128, MINB) k_dft_mma(const float* __restrict__ in,
                                                 float* __restrict__ out,
                                                 const float4* __restrict__ A4,
                                                 int rowLen2, size_t inStride2,
                                                 size_t outStride2){
  constexpr int KT = K/8;
  constexpr int MT = M/16;
  constexpr int PH = (K/2)*72;
  __shared__ __align__(16) float Bs[2*PH];
  int tid = threadIdx.x;
  {
    const float* src = in + (size_t)blockIdx.y*inStride2 + blockIdx.x*64;
    for (int i = tid; i < K*16; i += 128){
      int k = i >> 4, c4 = (i & 15)*4;
      float4 v = *(const float4*)(src + (size_t)k*rowLen2 + c4);
      float4 t = make_float4(tf32f(v.x), tf32f(v.y), tf32f(v.z), tf32f(v.w));
      *(float4*)(Bs + ((k>>2)&1)*PH + ((k>>3)*4 + (k&3))*72 + c4) = t;
    }
  }
  __syncthreads();
  int warp = tid>>5, lane = tid&31;
  int qid = lane>>2, rid = lane&3;
  int wcol = warp*16;
  float4 C[2][MT][2];
#pragma unroll
  for (int a=0;a<2;a++)
#pragma unroll
    for (int b=0;b<MT;b++)
#pragma unroll
      for (int c=0;c<2;c++) C[a][b][c] = make_float4(0.f,0.f,0.f,0.f);
#pragma unroll
  for (int kk=0; kk<KT; kk++){
    int sb = (kk*4 + rid)*72;
    float b00 = Bs[sb + wcol + qid];
    float b01 = Bs[PH + sb + wcol + qid];
    float b10 = Bs[sb + wcol + 8 + qid];
    float b11 = Bs[PH + sb + wcol + 8 + qid];
#pragma unroll
    for (int mm=0; mm<2; mm++){
#pragma unroll
      for (int mt=0; mt<MT; mt++){
        float4 af = __ldg(A4 + ((mm*KT+kk)*MT+mt)*32 + lane);
        mma8(C[mm][mt][0], af.x, af.y, af.z, af.w, b00, b01);
        mma8(C[mm][mt][1], af.x, af.y, af.z, af.w, b10, b11);
      }
    }
  }
  float* ob = out + (size_t)blockIdx.y*outStride2 + blockIdx.x*64;
#pragma unroll
  for (int mt=0; mt<MT; mt++){
#pragma unroll
    for (int nt=0; nt<2; nt++){
      float4 cr = C[0][mt][nt], ci = C[1][mt][nt];
      int col = wcol + nt*8 + rid*2;
      int m0 = mt*16 + qid;
      float2 v0, v1;
      if (SGN > 0){
        v0 = make_float2(cr.x + ci.y, cr.y - ci.x);
        v1 = make_float2(cr.z + ci.w, cr.w - ci.z);
      } else {
        v0 = make_float2(cr.x - ci.y, cr.y + ci.x);
        v1 = make_float2(cr.z - ci.w, cr.w + ci.z);
      }
      *(float2*)(ob + (size_t)m0*rowLen2 + col) = v0;
      *(float2*)(ob + (size_t)(m0+8)*rowLen2 + col) = v1;
    }
  }
}

// ---------------- K_mid: fwd-H + MLP + inv-H in place (pair-split layouts) ----------------
// smem floats: sW[4096]@0 | sBias[272]@4096 | U[8704]@4368 (2x 32 slices x 136) |
//              U2[4352]@13072 (2x 16 slices x 136).  Total 17424 fl = 69696 B
__global__ void __launch_bounds__(256,3) k_mid(){
  extern __shared__ float sm[];
  float* sW    = sm;
  float* sBias = sm + 4096;
  float* U     = sm + 4368;
  float* U2    = sm + 13072;
  const int PH1 = 4352;   // 32*136
  const int PH2 = 2176;   // 16*136
  int tid = threadIdx.x;
  int bx = blockIdx.x, b = blockIdx.y;
  int w = bx>>4, l = (bx>>1)&7, chalf = bx&1;
  for (int i=tid; i<1024; i+=256){
    int mg=i>>8, nb0=(i>>6)&3;
    ((float4*)sW)[i] = ((const float4*)g_W)[(mg*8+chalf*4+nb0)*64 + (i&63)];
  }
  { int mg=tid>>6, nb0=(tid>>4)&3, o=tid&15;
    sBias[(mg*4+nb0)*17+o] = g_Bias[mg*128 + (chalf*4+nb0)*16 + o]; }
  float2* gs = g_s2 + (size_t)b*2097152 + (size_t)w*1024 + l*128 + chalf*64;
  for (int i=tid; i<4096; i+=256){
    int yy=i>>6, c2=i&63;
    float2 v = gs[(size_t)yy*32768 + c2];
    float* d = U + ((yy>>2)&1)*PH1 + ((yy>>3)*4+(yy&3))*136 + 2*c2;
    *(float2*)d = make_float2(tf32f(v.x), tf32f(v.y));
  }
  __syncthreads();
  int warp=tid>>5, lane=tid&31, qid=lane>>2, rid=lane&3;
  // GEMM1 fwd-H: M=32,K=64,N=128
  float4 C1[2][2][2];
#pragma unroll
  for (int a=0;a<2;a++)
#pragma unroll
    for (int m=0;m<2;m++)
#pragma unroll
      for (int n=0;n<2;n++) C1[a][m][n] = make_float4(0.f,0.f,0.f,0.f);
#pragma unroll
  for (int kk=0; kk<8; kk++){
    int sb = (kk*4+rid)*136;
    float b00 = U[sb + warp*16 + qid];
    float b01 = U[PH1 + sb + warp*16 + qid];
    float b10 = U[sb + warp*16 + 8 + qid];
    float b11 = U[PH1 + sb + warp*16 + 8 + qid];
#pragma unroll
    for (int mat=0; mat<2; mat++){
#pragma unroll
      for (int mt=0; mt<2; mt++){
        float4 af = __ldg(&g_A4W[((mat*8+kk)*2+mt)*32 + lane]);
        mma8(C1[mat][mt][0], af.x,af.y,af.z,af.w, b00, b01);
        mma8(C1[mat][mt][1], af.x,af.y,af.z,af.w, b10, b11);
      }
    }
  }
  __syncthreads();
  float2* sSpec = (float2*)U;   // stride 65 f2; 8320 floats <= 8704
#pragma unroll
  for (int mt=0; mt<2; mt++)
#pragma unroll
    for (int nt=0; nt<2; nt++){
      float4 cc = C1[0][mt][nt], cs = C1[1][mt][nt];
      int c2 = warp*8+nt*4+rid, h0 = mt*16+qid;
      sSpec[h0*65 + c2]     = make_float2(cc.x+cs.y, cc.y-cs.x);
      sSpec[(h0+8)*65 + c2] = make_float2(cc.z+cs.w, cc.w-cs.z);
    }
  __syncthreads();
  // MLP: inst=(nb0,h), 2 threads each (half)
  {
    int inst=tid>>1, half=tid&1, nb0=inst>>5, h=inst&31;
    const float* W1R = sW + nb0*256;
    const float* W1I = sW + (4+nb0)*256;
    const float* W2R = sW + (8+nb0)*256;
    const float* W2I = sW + (12+nb0)*256;
    const float* Bb0 = sBias + nb0*17;
    const float* Bb1 = sBias + (4+nb0)*17;
    const float* Bb2 = sBias + (8+nb0)*17;
    const float* Bb3 = sBias + (12+nb0)*17;
    float xr[16], xi[16];
#pragma unroll
    for (int i=0;i<16;i++){ float2 v = sSpec[h*65 + nb0*16 + i]; xr[i]=v.x; xi[i]=v.y; }
    float pr[16], pi[16];
#pragma unroll
    for (int o=0;o<16;o++){ pr[o]=Bb0[o]; pi[o]=Bb1[o]; }
#pragma unroll
    for (int i=0;i<16;i++){
      float xrv = xr[i], xiv = xi[i];
#pragma unroll
      for (int o4=0;o4<4;o4++){
        float4 wr = *(const float4*)(W1R + i*16 + o4*4);
        float4 wi = *(const float4*)(W1I + i*16 + o4*4);
        pr[o4*4+0] += xrv*wr.x - xiv*wi.x;  pi[o4*4+0] += xiv*wr.x + xrv*wi.x;
        pr[o4*4+1] += xrv*wr.y - xiv*wi.y;  pi[o4*4+1] += xiv*wr.y + xrv*wi.y;
        pr[o4*4+2] += xrv*wr.z - xiv*wi.z;  pi[o4*4+2] += xiv*wr.z + xrv*wi.z;
        pr[o4*4+3] += xrv*wr.w - xiv*wi.w;  pi[o4*4+3] += xiv*wr.w + xrv*wi.w;
      }
    }
#pragma unroll
    for (int o=0;o<16;o++){ pr[o]=gelu_f(pr[o]); pi[o]=gelu_f(pi[o]); }
    float qr[8], qi[8];
#pragma unroll
    for (int oo=0;oo<8;oo++){ int o=half*8+oo; qr[oo]=Bb2[o]; qi[oo]=Bb3[o]; }
#pragma unroll
    for (int i=0;i<16;i++){
      float prv = pr[i], piv = pi[i];
#pragma unroll
      for (int o4=0;o4<2;o4++){
        float4 wr = *(const float4*)(W2R + i*16 + half*8 + o4*4);
        float4 wi = *(const float4*)(W2I + i*16 + half*8 + o4*4);
        qr[o4*4+0] += prv*wr.x - piv*wi.x;  qi[o4*4+0] += piv*wr.x + prv*wi.x;
        qr[o4*4+1] += prv*wr.y - piv*wi.y;  qi[o4*4+1] += piv*wr.y + prv*wi.y;
        qr[o4*4+2] += prv*wr.z - piv*wi.z;  qi[o4*4+2] += piv*wr.z + prv*wi.z;
        qr[o4*4+3] += prv*wr.w - piv*wi.w;  qi[o4*4+3] += piv*wr.w + prv*wi.w;
      }
    }
    float* d = U2 + ((h>>2)&1)*PH2 + ((h>>3)*4+(h&3))*136 + 2*(nb0*16+half*8);
#pragma unroll
    for (int j=0;j<4;j++){
      *(float4*)(d + 4*j) = make_float4(tf32f(qr[2*j]), tf32f(qi[2*j]),
                                        tf32f(qr[2*j+1]), tf32f(qi[2*j+1]));
    }
  }
  __syncthreads();
  // GEMM2 inv-H: M=64,K=32,N=128
  float4 C3[2][4][2];
#pragma unroll
  for (int a=0;a<2;a++)
#pragma unroll
    for (int m=0;m<4;m++)
#pragma unroll
      for (int n=0;n<2;n++) C3[a][m][n] = make_float4(0.f,0.f,0.f,0.f);
#pragma unroll
  for (int kk=0; kk<4; kk++){
    int sb = (kk*4+rid)*136;
    float b00 = U2[sb + warp*16 + qid];
    float b01 = U2[PH2 + sb + warp*16 + qid];
    float b10 = U2[sb + warp*16 + 8 + qid];
    float b11 = U2[PH2 + sb + warp*16 + 8 + qid];
#pragma unroll
    for (int mat=0; mat<2; mat++){
#pragma unroll
      for (int mt=0; mt<4; mt++){
        float4 af = __ldg(&g_A4Wi[((mat*4+kk)*4+mt)*32 + lane]);
        mma8(C3[mat][mt][0], af.x,af.y,af.z,af.w, b00, b01);
        mma8(C3[mat][mt][1], af.x,af.y,af.z,af.w, b10, b11);
      }
    }
  }
#pragma unroll
  for (int mt=0; mt<4; mt++)
#pragma unroll
    for (int nt=0; nt<2; nt++){
      float4 cc = C3[0][mt][nt], cs = C3[1][mt][nt];
      int c2 = warp*8+nt*4+rid, y0 = mt*16+qid;
      gs[(size_t)y0*32768 + c2]     = make_float2(cc.x-cs.y, cc.y+cs.x);
      gs[(size_t)(y0+8)*32768 + c2] = make_float2(cc.z-cs.w, cc.w+cs.z);
    }
}

// ---------------- K7: inverse rfft over L (radix-2) + residual ----------------
__global__ void k_inv_l(const float* __restrict__ xin, float* __restrict__ out){
  __shared__ float2 tw[32];
  if (threadIdx.x < 32) tw[threadIdx.x] = TW32[threadIdx.x];
  __syncthreads();
  int tid = blockIdx.x*blockDim.x + threadIdx.x;
  int c = tid & 127;
  int site = tid >> 7;
  const float2* ip = g_s3 + (size_t)site*1024 + c;
  float Xr[8], Xi[8];
#pragma unroll
  for (int l=0;l<8;l++){ float2 v = ip[l*128]; Xr[l]=v.x; Xi[l]=v.y; }
#pragma unroll
  for (int l=1;l<8;l++){ Xr[l]*=2.f; Xi[l]*=2.f; }
  const float s = 0.1767766952966369f;
  const float* rp = xin + (size_t)site*4096 + c;
  float* op = out + (size_t)site*4096 + c;
#pragma unroll
  for (int t=0;t<16;t++){
    float E = Xr[0];
    float O = 0.f;
#pragma unroll
    for (int j=1;j<4;j++){
      float2 we = tw[(2*j*t)&31];
      E += Xr[2*j]*we.x - Xi[2*j]*we.y;
    }
#pragma unroll
    for (int j=0;j<4;j++){
      float2 wo = tw[((2*j+1)*t)&31];
      O += Xr[2*j+1]*wo.x - Xi[2*j+1]*wo.y;
    }
    op[t*128]      = fmaf(E+O, s, rp[t*128]);
    op[(t+16)*128] = fmaf(E-O, s, rp[(t+16)*128]);
  }
}

// ---------------- launch ----------------
extern "C" void kernel_launch(void* const* d_in, const int* in_sizes, int n_in,
                              void* d_out, int out_size){
  (void)in_sizes; (void)n_in; (void)out_size;
  const float* x = (const float*)d_in[0];
  void *ps3, *ps2, *paw, *pawi;
  cudaGetSymbolAddress(&ps3,  g_s3);
  cudaGetSymbolAddress(&ps2,  g_s2);
  cudaGetSymbolAddress(&paw,  g_A4W);
  cudaGetSymbolAddress(&pawi, g_A4Wi);
  const float* s3 = (const float*)ps3;
  const float* s2 = (const float*)ps2;
  const float4* aw  = (const float4*)paw;
  const float4* awi = (const float4*)pawi;
  cudaFuncSetAttribute(k_mid, cudaFuncAttributeMaxDynamicSharedMemorySize, 69696);

  k_prep<<<8,256>>>((const float*)d_in[1], (const float*)d_in[2], (const float*)d_in[3],
                    (const float*)d_in[4], (const float*)d_in[5], (const float*)d_in[6],
                    (const float*)d_in[7], (const float*)d_in[8], (const float*)d_in[9],
                    (const float*)d_in[10], (const float*)d_in[11], (const float*)d_in[12],
                    (const float*)d_in[13]);
  k_init4<<<8,256>>>();
  k_fwd_l<<<16384,128>>>(x);
  // fwd W: Out[32][1024c] = T @ In[64][1024c], 256 (b,y) batches
  k_dft_mma<32,64, 1,8><<<dim3(32,256),128>>>(s3, (float*)s2, aw, 2048, 131072, 65536);
  // fwd H + MLP + inv H, in place on g_s2
  k_mid<<<dim3(512,4),256,69696>>>();
  // inv W: Out[64][1024c] = T @ In[32][1024c]
  k_dft_mma<64,32,-1,6><<<dim3(32,256),128>>>(s2, (float*)s3, awi, 2048, 65536, 131072);
  k_inv_l<<<16384,128>>>(x, (float*)d_out);
}